// round 4
// baseline (speedup 1.0000x reference)
#include <cuda_runtime.h>

#define N_NODES 100000
#define FEAT 64
#define EPP 3200000
#define NPATH 3
#define HIDDEN 128
#define N16 (N_NODES * 16)   // float4 count of a [N,64] array

// ---------------- scratch (static device globals; no runtime alloc) ----------------
__device__ float g_X[N_NODES * FEAT];            // relu(h)
__device__ float g_sf[N_NODES * FEAT];           // feat * norm_out (gather source)
__device__ float g_acc[N_NODES * FEAT];          // scatter accumulator
__device__ float g_z[NPATH * N_NODES * FEAT];    // per-path propagated features
__device__ float g_no[N_NODES];                  // norm_out
__device__ float g_ni[N_NODES];                  // norm_in
__device__ int   g_dego[N_NODES];
__device__ int   g_degi[N_NODES];
__device__ float g_wsum[NPATH];
__device__ float g_beta[NPATH];

// ---------------- helpers ----------------
__device__ __forceinline__ float tanh_fast(float x) {
    float y;
    asm("tanh.approx.f32 %0, %1;" : "=f"(y) : "f"(x));
    return y;
}

__device__ __forceinline__ void red_add_v4(float* p, float4 v) {
    asm volatile("red.global.add.v4.f32 [%0], {%1, %2, %3, %4};"
                 :: "l"(p), "f"(v.x), "f"(v.y), "f"(v.z), "f"(v.w)
                 : "memory");
}

// ---------------- kernels ----------------
__global__ void k_relu(const float4* __restrict__ h) {
    int i = blockIdx.x * blockDim.x + threadIdx.x;
    if (i < N16) {
        float4 v = h[i];
        v.x = fmaxf(v.x, 0.f); v.y = fmaxf(v.y, 0.f);
        v.z = fmaxf(v.z, 0.f); v.w = fmaxf(v.w, 0.f);
        reinterpret_cast<float4*>(g_X)[i] = v;
    }
    if (i < NPATH) g_wsum[i] = 0.f;
}

__global__ void k_zero_deg() {
    int i = blockIdx.x * blockDim.x + threadIdx.x;
    if (i < N_NODES) { g_dego[i] = 0; g_degi[i] = 0; }
}

__global__ void k_deg(const int* __restrict__ src, const int* __restrict__ dst) {
    int i = blockIdx.x * blockDim.x + threadIdx.x;
    if (i < EPP) {
        atomicAdd(&g_dego[src[i]], 1);
        atomicAdd(&g_degi[dst[i]], 1);
    }
}

__global__ void k_norm() {
    int i = blockIdx.x * blockDim.x + threadIdx.x;
    if (i < N_NODES) {
        g_no[i] = rsqrtf((float)max(g_dego[i], 1));
        g_ni[i] = rsqrtf((float)max(g_degi[i], 1));
    }
}

// step 0: sf = X * norm_out ; acc = 0
__global__ void k_prescale0() {
    int i = blockIdx.x * blockDim.x + threadIdx.x;
    if (i < N16) {
        float no = g_no[i >> 4];
        float4 v = reinterpret_cast<const float4*>(g_X)[i];
        v.x *= no; v.y *= no; v.z *= no; v.w *= no;
        reinterpret_cast<float4*>(g_sf)[i] = v;
        reinterpret_cast<float4*>(g_acc)[i] = make_float4(0.f, 0.f, 0.f, 0.f);
    }
}

// mid steps: sf = (0.9*ni*acc + 0.1*X) * no ; acc = 0
__global__ void k_finpre() {
    int i = blockIdx.x * blockDim.x + threadIdx.x;
    if (i < N16) {
        int n = i >> 4;
        float ni = 0.9f * g_ni[n];
        float no = g_no[n];
        float4 a = reinterpret_cast<const float4*>(g_acc)[i];
        float4 x = reinterpret_cast<const float4*>(g_X)[i];
        float4 s;
        s.x = (fmaf(ni, a.x, 0.1f * x.x)) * no;
        s.y = (fmaf(ni, a.y, 0.1f * x.y)) * no;
        s.z = (fmaf(ni, a.z, 0.1f * x.z)) * no;
        s.w = (fmaf(ni, a.w, 0.1f * x.w)) * no;
        reinterpret_cast<float4*>(g_sf)[i] = s;
        reinterpret_cast<float4*>(g_acc)[i] = make_float4(0.f, 0.f, 0.f, 0.f);
    }
}

// last step: z_p = 0.9*ni*acc + 0.1*X
__global__ void k_final(int p) {
    int i = blockIdx.x * blockDim.x + threadIdx.x;
    if (i < N16) {
        int n = i >> 4;
        float ni = 0.9f * g_ni[n];
        float4 a = reinterpret_cast<const float4*>(g_acc)[i];
        float4 x = reinterpret_cast<const float4*>(g_X)[i];
        float4 r;
        r.x = fmaf(ni, a.x, 0.1f * x.x);
        r.y = fmaf(ni, a.y, 0.1f * x.y);
        r.z = fmaf(ni, a.z, 0.1f * x.z);
        r.w = fmaf(ni, a.w, 0.1f * x.w);
        reinterpret_cast<float4*>(g_z)[(size_t)p * N16 + i] = r;
    }
}

// edge scatter: 16 threads per edge, float4 gather + float4 reduction
__global__ void k_scatter(const int* __restrict__ src, const int* __restrict__ dst) {
    unsigned tid = blockIdx.x * blockDim.x + threadIdx.x;
    unsigned e = tid >> 4;
    unsigned l = tid & 15u;
    if (e >= EPP) return;
    int s = __ldg(&src[e]);
    int d = __ldg(&dst[e]);
    float4 v = __ldg(reinterpret_cast<const float4*>(g_sf) + (size_t)s * 16 + l);
    float* p = reinterpret_cast<float*>(reinterpret_cast<float4*>(g_acc) + (size_t)d * 16 + l);
    red_add_v4(p, v);
}

// semantic fusion: one warp per node-path, W1 staged in shared
__global__ void k_fusion(const float* __restrict__ W1, const float* __restrict__ b1,
                         const float* __restrict__ W2) {
    __shared__ __align__(16) float W1s[FEAT * HIDDEN];   // 32 KB
    __shared__ float zs[8][FEAT];                        // 2 KB
    int tid = threadIdx.x;
    for (int i = tid; i < FEAT * HIDDEN; i += blockDim.x) W1s[i] = W1[i];
    __syncthreads();

    int lane = tid & 31;
    int w = tid >> 5;
    float4 b4 = reinterpret_cast<const float4*>(b1)[lane];
    float4 w24 = reinterpret_cast<const float4*>(W2)[lane];
    int warpsTotal = gridDim.x * 8;

    for (int np = blockIdx.x * 8 + w; np < NPATH * N_NODES; np += warpsTotal) {
        float2 v = reinterpret_cast<const float2*>(g_z)[(size_t)np * 32 + lane];
        zs[w][2 * lane] = v.x;
        zs[w][2 * lane + 1] = v.y;
        __syncwarp();
        float4 acc = make_float4(0.f, 0.f, 0.f, 0.f);
#pragma unroll
        for (int j = 0; j < FEAT; j++) {
            float zj = zs[w][j];
            float4 ww = reinterpret_cast<const float4*>(W1s)[j * 32 + lane];
            acc.x = fmaf(zj, ww.x, acc.x);
            acc.y = fmaf(zj, ww.y, acc.y);
            acc.z = fmaf(zj, ww.z, acc.z);
            acc.w = fmaf(zj, ww.w, acc.w);
        }
        __syncwarp();
        float s = tanh_fast(acc.x + b4.x) * w24.x
                + tanh_fast(acc.y + b4.y) * w24.y
                + tanh_fast(acc.z + b4.z) * w24.z
                + tanh_fast(acc.w + b4.w) * w24.w;
#pragma unroll
        for (int o = 16; o; o >>= 1) s += __shfl_xor_sync(0xffffffffu, s, o);
        if (lane == 0) atomicAdd(&g_wsum[np / N_NODES], s);
    }
}

__global__ void k_beta() {
    if (threadIdx.x == 0) {
        float w0 = g_wsum[0] / (float)N_NODES;
        float w1 = g_wsum[1] / (float)N_NODES;
        float w2 = g_wsum[2] / (float)N_NODES;
        float m = fmaxf(w0, fmaxf(w1, w2));
        float e0 = expf(w0 - m), e1 = expf(w1 - m), e2 = expf(w2 - m);
        float inv = 1.f / (e0 + e1 + e2);
        g_beta[0] = e0 * inv; g_beta[1] = e1 * inv; g_beta[2] = e2 * inv;
    }
}

__global__ void k_out(float4* __restrict__ out) {
    int i = blockIdx.x * blockDim.x + threadIdx.x;
    if (i < N16) {
        float b0 = g_beta[0], b1 = g_beta[1], b2 = g_beta[2];
        const float4* z = reinterpret_cast<const float4*>(g_z);
        float4 z0 = z[i];
        float4 z1 = z[N16 + i];
        float4 z2 = z[2 * (size_t)N16 + i];
        float4 r;
        r.x = b0 * z0.x + b1 * z1.x + b2 * z2.x;
        r.y = b0 * z0.y + b1 * z1.y + b2 * z2.y;
        r.z = b0 * z0.z + b1 * z1.z + b2 * z2.z;
        r.w = b0 * z0.w + b1 * z1.w + b2 * z2.w;
        out[i] = r;
    }
}

// ---------------- launch ----------------
extern "C" void kernel_launch(void* const* d_in, const int* in_sizes, int n_in,
                              void* d_out, int out_size) {
    const float* h  = (const float*)d_in[0];
    const int* src  = (const int*)d_in[1];   // JAX default x64-disabled -> int32
    const int* dst  = (const int*)d_in[2];
    const float* W1 = (const float*)d_in[3];
    const float* b1 = (const float*)d_in[4];
    const float* W2 = (const float*)d_in[5];

    const int TB = 256;
    const int gElem = (N16 + TB - 1) / TB;               // 6250
    const int gNode = (N_NODES + TB - 1) / TB;           // 391
    const int gEdge = (EPP + TB - 1) / TB;               // 12500
    const int gScat = (int)(((long long)EPP * 16 + TB - 1) / TB);  // 200000

    k_relu<<<gElem, TB>>>((const float4*)h);

    for (int p = 0; p < NPATH; p++) {
        const int* sp = src + (size_t)p * EPP;
        const int* dp = dst + (size_t)p * EPP;
        k_zero_deg<<<gNode, TB>>>();
        k_deg<<<gEdge, TB>>>(sp, dp);
        k_norm<<<gNode, TB>>>();

        k_prescale0<<<gElem, TB>>>();
        k_scatter<<<gScat, TB>>>(sp, dp);
        k_finpre<<<gElem, TB>>>();
        k_scatter<<<gScat, TB>>>(sp, dp);
        k_finpre<<<gElem, TB>>>();
        k_scatter<<<gScat, TB>>>(sp, dp);
        k_final<<<gElem, TB>>>(p);
    }

    k_fusion<<<1184, 256>>>(W1, b1, W2);
    k_beta<<<1, 32>>>();
    k_out<<<gElem, TB>>>((float4*)d_out);
}

// round 9
// speedup vs baseline: 1.8347x; 1.8347x over previous
#include <cuda_runtime.h>

#define N_NODES 100000
#define FEAT 64
#define EPP 3200000
#define NPATH 3
#define HIDDEN 128
#define N16 (N_NODES * 16)   // float4 count of a [N,64] array
#define NBLK 391             // ceil(N_NODES/256)

// ---------------- scratch (static device globals; no runtime alloc) ----------------
__device__ float g_X[N_NODES * FEAT];            // relu(h)
__device__ float g_sfA[N_NODES * FEAT];          // ping-pong gather buffers
__device__ float g_sfB[N_NODES * FEAT];
__device__ float g_z[NPATH * N_NODES * FEAT];    // per-path propagated features
__device__ float g_no[N_NODES];                  // norm_out
__device__ float g_ni[N_NODES];                  // norm_in
__device__ int   g_dego[N_NODES];
__device__ int   g_degi[N_NODES];
__device__ int   g_off[N_NODES + 1];             // CSR row offsets (by dst)
__device__ int   g_cursor[N_NODES];              // fill cursors
__device__ int   g_bsum[512];                    // per-block degree sums
__device__ int   g_csr[EPP];                     // CSR column indices (src)
__device__ float g_wsum[NPATH];
__device__ float g_beta[NPATH];

// ---------------- helpers ----------------
__device__ __forceinline__ float tanh_fast(float x) {
    float y;
    asm("tanh.approx.f32 %0, %1;" : "=f"(y) : "f"(x));
    return y;
}

// ---------------- kernels ----------------
__global__ void k_relu(const float4* __restrict__ h) {
    int i = blockIdx.x * blockDim.x + threadIdx.x;
    if (i < N16) {
        float4 v = h[i];
        v.x = fmaxf(v.x, 0.f); v.y = fmaxf(v.y, 0.f);
        v.z = fmaxf(v.z, 0.f); v.w = fmaxf(v.w, 0.f);
        reinterpret_cast<float4*>(g_X)[i] = v;
    }
    if (i < NPATH) g_wsum[i] = 0.f;
}

__global__ void k_zero_deg() {
    int i = blockIdx.x * blockDim.x + threadIdx.x;
    if (i < N_NODES) { g_dego[i] = 0; g_degi[i] = 0; }
}

__global__ void k_deg(const int* __restrict__ src, const int* __restrict__ dst) {
    int i = blockIdx.x * blockDim.x + threadIdx.x;
    if (i < EPP) {
        atomicAdd(&g_dego[src[i]], 1);
        atomicAdd(&g_degi[dst[i]], 1);
    }
}

__global__ void k_norm() {
    int i = blockIdx.x * blockDim.x + threadIdx.x;
    if (i < N_NODES) {
        g_no[i] = rsqrtf((float)max(g_dego[i], 1));
        g_ni[i] = rsqrtf((float)max(g_degi[i], 1));
    }
}

// --- CSR build: scan degi into offsets ---
__global__ void k_bsum() {
    __shared__ int s[256];
    int t = threadIdx.x;
    int i = blockIdx.x * 256 + t;
    s[t] = (i < N_NODES) ? g_degi[i] : 0;
    __syncthreads();
    for (int d = 128; d > 0; d >>= 1) {
        if (t < d) s[t] += s[t + d];
        __syncthreads();
    }
    if (t == 0) g_bsum[blockIdx.x] = s[0];
}

__global__ void k_bscan() {   // 1 block, 512 threads: exclusive scan of block sums
    __shared__ int s[512];
    int t = threadIdx.x;
    int v = (t < NBLK) ? g_bsum[t] : 0;
    s[t] = v;
    __syncthreads();
    for (int d = 1; d < 512; d <<= 1) {
        int x = (t >= d) ? s[t - d] : 0;
        __syncthreads();
        s[t] += x;
        __syncthreads();
    }
    g_bsum[t] = s[t] - v;     // exclusive
    if (t == 0) g_off[N_NODES] = EPP;
}

__global__ void k_offsets() {
    __shared__ int s[256];
    int t = threadIdx.x;
    int i = blockIdx.x * 256 + t;
    int v = (i < N_NODES) ? g_degi[i] : 0;
    s[t] = v;
    __syncthreads();
    for (int d = 1; d < 256; d <<= 1) {
        int x = (t >= d) ? s[t - d] : 0;
        __syncthreads();
        s[t] += x;
        __syncthreads();
    }
    if (i < N_NODES) {
        int off = g_bsum[blockIdx.x] + s[t] - v;  // exclusive
        g_off[i] = off;
        g_cursor[i] = off;
    }
}

__global__ void k_fill(const int* __restrict__ src, const int* __restrict__ dst) {
    int i = blockIdx.x * blockDim.x + threadIdx.x;
    if (i < EPP) {
        int pos = atomicAdd(&g_cursor[dst[i]], 1);
        g_csr[pos] = src[i];
    }
}

// step 0: sfA = X * norm_out
__global__ void k_prescale0() {
    int i = blockIdx.x * blockDim.x + threadIdx.x;
    if (i < N16) {
        float no = g_no[i >> 4];
        float4 v = reinterpret_cast<const float4*>(g_X)[i];
        v.x *= no; v.y *= no; v.z *= no; v.w *= no;
        reinterpret_cast<float4*>(g_sfA)[i] = v;
    }
}

// CSR gather-reduce + fused finalize (+prescale for mid steps)
// 16 lanes per dst node; float4 accumulator per lane.
// rdA: read from g_sfA (else g_sfB). Writes go to the OTHER buffer (or g_z if last).
__global__ void k_gather(int rdA, int last, int p) {
    unsigned tid = blockIdx.x * blockDim.x + threadIdx.x;
    unsigned n = tid >> 4;
    unsigned l = tid & 15u;
    if (n >= N_NODES) return;

    int beg = g_off[n];
    int end = g_off[n + 1];
    const float4* sf4 = reinterpret_cast<const float4*>(rdA ? g_sfA : g_sfB);

    float4 acc = make_float4(0.f, 0.f, 0.f, 0.f);
    int e = beg;
    for (; e + 4 <= end; e += 4) {
        int s0 = __ldg(&g_csr[e]);
        int s1 = __ldg(&g_csr[e + 1]);
        int s2 = __ldg(&g_csr[e + 2]);
        int s3 = __ldg(&g_csr[e + 3]);
        float4 v0 = __ldg(sf4 + (size_t)s0 * 16 + l);
        float4 v1 = __ldg(sf4 + (size_t)s1 * 16 + l);
        float4 v2 = __ldg(sf4 + (size_t)s2 * 16 + l);
        float4 v3 = __ldg(sf4 + (size_t)s3 * 16 + l);
        acc.x += (v0.x + v1.x) + (v2.x + v3.x);
        acc.y += (v0.y + v1.y) + (v2.y + v3.y);
        acc.z += (v0.z + v1.z) + (v2.z + v3.z);
        acc.w += (v0.w + v1.w) + (v2.w + v3.w);
    }
    for (; e < end; e++) {
        int s = __ldg(&g_csr[e]);
        float4 v = __ldg(sf4 + (size_t)s * 16 + l);
        acc.x += v.x; acc.y += v.y; acc.z += v.z; acc.w += v.w;
    }

    float ni = 0.9f * g_ni[n];
    float4 x = reinterpret_cast<const float4*>(g_X)[n * 16 + l];
    float4 r;
    r.x = fmaf(ni, acc.x, 0.1f * x.x);
    r.y = fmaf(ni, acc.y, 0.1f * x.y);
    r.z = fmaf(ni, acc.z, 0.1f * x.z);
    r.w = fmaf(ni, acc.w, 0.1f * x.w);

    if (last) {
        reinterpret_cast<float4*>(g_z)[(size_t)p * N16 + n * 16 + l] = r;
    } else {
        float no = g_no[n];
        r.x *= no; r.y *= no; r.z *= no; r.w *= no;
        float4* wr = reinterpret_cast<float4*>(rdA ? g_sfB : g_sfA);
        wr[n * 16 + l] = r;
    }
}

// semantic fusion: one warp per node-path, W1 staged in shared
__global__ void k_fusion(const float* __restrict__ W1, const float* __restrict__ b1,
                         const float* __restrict__ W2) {
    __shared__ __align__(16) float W1s[FEAT * HIDDEN];   // 32 KB
    __shared__ float zs[8][FEAT];                        // 2 KB
    int tid = threadIdx.x;
    for (int i = tid; i < FEAT * HIDDEN; i += blockDim.x) W1s[i] = W1[i];
    __syncthreads();

    int lane = tid & 31;
    int w = tid >> 5;
    float4 b4 = reinterpret_cast<const float4*>(b1)[lane];
    float4 w24 = reinterpret_cast<const float4*>(W2)[lane];
    int warpsTotal = gridDim.x * 8;

    for (int np = blockIdx.x * 8 + w; np < NPATH * N_NODES; np += warpsTotal) {
        float2 v = reinterpret_cast<const float2*>(g_z)[(size_t)np * 32 + lane];
        zs[w][2 * lane] = v.x;
        zs[w][2 * lane + 1] = v.y;
        __syncwarp();
        float4 acc = make_float4(0.f, 0.f, 0.f, 0.f);
#pragma unroll
        for (int j = 0; j < FEAT; j++) {
            float zj = zs[w][j];
            float4 ww = reinterpret_cast<const float4*>(W1s)[j * 32 + lane];
            acc.x = fmaf(zj, ww.x, acc.x);
            acc.y = fmaf(zj, ww.y, acc.y);
            acc.z = fmaf(zj, ww.z, acc.z);
            acc.w = fmaf(zj, ww.w, acc.w);
        }
        __syncwarp();
        float s = tanh_fast(acc.x + b4.x) * w24.x
                + tanh_fast(acc.y + b4.y) * w24.y
                + tanh_fast(acc.z + b4.z) * w24.z
                + tanh_fast(acc.w + b4.w) * w24.w;
#pragma unroll
        for (int o = 16; o; o >>= 1) s += __shfl_xor_sync(0xffffffffu, s, o);
        if (lane == 0) atomicAdd(&g_wsum[np / N_NODES], s);
    }
}

__global__ void k_beta() {
    if (threadIdx.x == 0) {
        float w0 = g_wsum[0] / (float)N_NODES;
        float w1 = g_wsum[1] / (float)N_NODES;
        float w2 = g_wsum[2] / (float)N_NODES;
        float m = fmaxf(w0, fmaxf(w1, w2));
        float e0 = expf(w0 - m), e1 = expf(w1 - m), e2 = expf(w2 - m);
        float inv = 1.f / (e0 + e1 + e2);
        g_beta[0] = e0 * inv; g_beta[1] = e1 * inv; g_beta[2] = e2 * inv;
    }
}

__global__ void k_out(float4* __restrict__ out) {
    int i = blockIdx.x * blockDim.x + threadIdx.x;
    if (i < N16) {
        float b0 = g_beta[0], b1 = g_beta[1], b2 = g_beta[2];
        const float4* z = reinterpret_cast<const float4*>(g_z);
        float4 z0 = z[i];
        float4 z1 = z[N16 + i];
        float4 z2 = z[2 * (size_t)N16 + i];
        float4 r;
        r.x = b0 * z0.x + b1 * z1.x + b2 * z2.x;
        r.y = b0 * z0.y + b1 * z1.y + b2 * z2.y;
        r.z = b0 * z0.z + b1 * z1.z + b2 * z2.z;
        r.w = b0 * z0.w + b1 * z1.w + b2 * z2.w;
        out[i] = r;
    }
}

// ---------------- launch ----------------
extern "C" void kernel_launch(void* const* d_in, const int* in_sizes, int n_in,
                              void* d_out, int out_size) {
    const float* h  = (const float*)d_in[0];
    const int* src  = (const int*)d_in[1];   // JAX x64-disabled -> int32
    const int* dst  = (const int*)d_in[2];
    const float* W1 = (const float*)d_in[3];
    const float* b1 = (const float*)d_in[4];
    const float* W2 = (const float*)d_in[5];

    const int TB = 256;
    const int gElem = (N16 + TB - 1) / TB;               // 6250
    const int gNode = (N_NODES + TB - 1) / TB;           // 391
    const int gEdge = (EPP + TB - 1) / TB;               // 12500
    const int gGath = (int)(((long long)N_NODES * 16 + TB - 1) / TB);  // 6250

    k_relu<<<gElem, TB>>>((const float4*)h);

    for (int p = 0; p < NPATH; p++) {
        const int* sp = src + (size_t)p * EPP;
        const int* dp = dst + (size_t)p * EPP;

        k_zero_deg<<<gNode, TB>>>();
        k_deg<<<gEdge, TB>>>(sp, dp);
        k_norm<<<gNode, TB>>>();

        // CSR build (by dst), amortized over 3 steps
        k_bsum<<<NBLK, 256>>>();
        k_bscan<<<1, 512>>>();
        k_offsets<<<NBLK, 256>>>();
        k_fill<<<gEdge, TB>>>(sp, dp);

        k_prescale0<<<gElem, TB>>>();
        // ping-pong: A -> B -> A -> z  (read-set / write-set disjoint each step)
        k_gather<<<gGath, TB>>>(1, 0, p);   // read A, write B
        k_gather<<<gGath, TB>>>(0, 0, p);   // read B, write A
        k_gather<<<gGath, TB>>>(1, 1, p);   // read A, write z
    }

    k_fusion<<<1184, 256>>>(W1, b1, W2);
    k_beta<<<1, 32>>>();
    k_out<<<gElem, TB>>>((float4*)d_out);
}

// round 16
// speedup vs baseline: 2.0116x; 1.0964x over previous
#include <cuda_runtime.h>
#include <cuda_fp16.h>

#define N_NODES 100000
#define FEAT 64
#define EPP 3200000
#define NPATH 3
#define HIDDEN 128
#define N16 (N_NODES * 16)   // float4 count of a [N,64] array
#define NBLK 391             // ceil(N_NODES/256)

// ---------------- scratch (static device globals; no runtime alloc) ----------------
__device__ float g_X[N_NODES * FEAT];                       // relu(h)
__device__ __align__(16) __half g_sfA[N_NODES * FEAT];      // ping-pong fp16 message buffers
__device__ __align__(16) __half g_sfB[N_NODES * FEAT];
__device__ float g_z[NPATH * N_NODES * FEAT];               // per-path propagated features
__device__ float g_no[N_NODES];                             // norm_out
__device__ float g_ni[N_NODES];                             // norm_in
__device__ int   g_dego[N_NODES];
__device__ int   g_degi[N_NODES];
__device__ int   g_off[N_NODES + 1];                        // CSR row offsets (by dst)
__device__ int   g_cursor[N_NODES];                         // fill cursors
__device__ int   g_bsum[512];                               // per-block degree sums
__device__ int   g_csr[EPP];                                // CSR column indices (src)
__device__ float g_wsum[NPATH];
__device__ float g_beta[NPATH];

// ---------------- helpers ----------------
__device__ __forceinline__ float tanh_fast(float x) {
    float y;
    asm("tanh.approx.f32 %0, %1;" : "=f"(y) : "f"(x));
    return y;
}

// pack 4 floats -> uint2 of half2s
__device__ __forceinline__ uint2 pack4h(float a, float b, float c, float d) {
    __half2 h0 = __float22half2_rn(make_float2(a, b));
    __half2 h1 = __float22half2_rn(make_float2(c, d));
    uint2 u;
    u.x = *reinterpret_cast<unsigned*>(&h0);
    u.y = *reinterpret_cast<unsigned*>(&h1);
    return u;
}

__device__ __forceinline__ void unpack4h(uint2 u, float2& f0, float2& f1) {
    __half2 h0 = *reinterpret_cast<__half2*>(&u.x);
    __half2 h1 = *reinterpret_cast<__half2*>(&u.y);
    f0 = __half22float2(h0);
    f1 = __half22float2(h1);
}

// ---------------- kernels ----------------
__global__ void k_relu(const float4* __restrict__ h) {
    int i = blockIdx.x * blockDim.x + threadIdx.x;
    if (i < N16) {
        float4 v = h[i];
        v.x = fmaxf(v.x, 0.f); v.y = fmaxf(v.y, 0.f);
        v.z = fmaxf(v.z, 0.f); v.w = fmaxf(v.w, 0.f);
        reinterpret_cast<float4*>(g_X)[i] = v;
    }
    if (i < NPATH) g_wsum[i] = 0.f;
}

__global__ void k_zero_deg() {
    int i = blockIdx.x * blockDim.x + threadIdx.x;
    if (i < N_NODES) { g_dego[i] = 0; g_degi[i] = 0; }
}

__global__ void k_deg(const int* __restrict__ src, const int* __restrict__ dst) {
    int i = blockIdx.x * blockDim.x + threadIdx.x;
    if (i < EPP) {
        atomicAdd(&g_dego[src[i]], 1);
        atomicAdd(&g_degi[dst[i]], 1);
    }
}

__global__ void k_norm() {
    int i = blockIdx.x * blockDim.x + threadIdx.x;
    if (i < N_NODES) {
        g_no[i] = rsqrtf((float)max(g_dego[i], 1));
        g_ni[i] = rsqrtf((float)max(g_degi[i], 1));
    }
}

// --- CSR build: scan degi into offsets ---
__global__ void k_bsum() {
    __shared__ int s[256];
    int t = threadIdx.x;
    int i = blockIdx.x * 256 + t;
    s[t] = (i < N_NODES) ? g_degi[i] : 0;
    __syncthreads();
    for (int d = 128; d > 0; d >>= 1) {
        if (t < d) s[t] += s[t + d];
        __syncthreads();
    }
    if (t == 0) g_bsum[blockIdx.x] = s[0];
}

__global__ void k_bscan() {   // 1 block, 512 threads: exclusive scan of block sums
    __shared__ int s[512];
    int t = threadIdx.x;
    int v = (t < NBLK) ? g_bsum[t] : 0;
    s[t] = v;
    __syncthreads();
    for (int d = 1; d < 512; d <<= 1) {
        int x = (t >= d) ? s[t - d] : 0;
        __syncthreads();
        s[t] += x;
        __syncthreads();
    }
    g_bsum[t] = s[t] - v;     // exclusive
    if (t == 0) g_off[N_NODES] = EPP;
}

__global__ void k_offsets() {
    __shared__ int s[256];
    int t = threadIdx.x;
    int i = blockIdx.x * 256 + t;
    int v = (i < N_NODES) ? g_degi[i] : 0;
    s[t] = v;
    __syncthreads();
    for (int d = 1; d < 256; d <<= 1) {
        int x = (t >= d) ? s[t - d] : 0;
        __syncthreads();
        s[t] += x;
        __syncthreads();
    }
    if (i < N_NODES) {
        int off = g_bsum[blockIdx.x] + s[t] - v;  // exclusive
        g_off[i] = off;
        g_cursor[i] = off;
    }
}

__global__ void k_fill(const int* __restrict__ src, const int* __restrict__ dst) {
    int i = blockIdx.x * blockDim.x + threadIdx.x;
    if (i < EPP) {
        int pos = atomicAdd(&g_cursor[dst[i]], 1);
        g_csr[pos] = src[i];
    }
}

// step 0: sfA = half(X * norm_out)
__global__ void k_prescale0() {
    int i = blockIdx.x * blockDim.x + threadIdx.x;
    if (i < N16) {
        float no = g_no[i >> 4];
        float4 v = reinterpret_cast<const float4*>(g_X)[i];
        reinterpret_cast<uint2*>(g_sfA)[i] =
            pack4h(v.x * no, v.y * no, v.z * no, v.w * no);
    }
}

// CSR gather-reduce + fused finalize (+prescale for mid steps)
// 16 lanes per dst node; 4 features (8 bytes fp16) per lane; fp32 accumulation.
// rdA: read from g_sfA (else g_sfB). Writes go to the OTHER buffer (or g_z if last).
__global__ void k_gather(int rdA, int last, int p) {
    unsigned tid = blockIdx.x * blockDim.x + threadIdx.x;
    unsigned n = tid >> 4;
    unsigned l = tid & 15u;
    if (n >= N_NODES) return;

    int beg = g_off[n];
    int end = g_off[n + 1];
    const uint2* sf2 = reinterpret_cast<const uint2*>(rdA ? g_sfA : g_sfB);

    float4 acc = make_float4(0.f, 0.f, 0.f, 0.f);
    int e = beg;
    for (; e + 4 <= end; e += 4) {
        int s0 = __ldg(&g_csr[e]);
        int s1 = __ldg(&g_csr[e + 1]);
        int s2 = __ldg(&g_csr[e + 2]);
        int s3 = __ldg(&g_csr[e + 3]);
        uint2 u0 = __ldg(sf2 + (size_t)s0 * 16 + l);
        uint2 u1 = __ldg(sf2 + (size_t)s1 * 16 + l);
        uint2 u2 = __ldg(sf2 + (size_t)s2 * 16 + l);
        uint2 u3 = __ldg(sf2 + (size_t)s3 * 16 + l);
        float2 a0, b0, a1, b1, a2, b2, a3, b3;
        unpack4h(u0, a0, b0);
        unpack4h(u1, a1, b1);
        unpack4h(u2, a2, b2);
        unpack4h(u3, a3, b3);
        acc.x += (a0.x + a1.x) + (a2.x + a3.x);
        acc.y += (a0.y + a1.y) + (a2.y + a3.y);
        acc.z += (b0.x + b1.x) + (b2.x + b3.x);
        acc.w += (b0.y + b1.y) + (b2.y + b3.y);
    }
    for (; e < end; e++) {
        int s = __ldg(&g_csr[e]);
        uint2 u = __ldg(sf2 + (size_t)s * 16 + l);
        float2 a, b;
        unpack4h(u, a, b);
        acc.x += a.x; acc.y += a.y; acc.z += b.x; acc.w += b.y;
    }

    float ni = 0.9f * g_ni[n];
    float4 x = reinterpret_cast<const float4*>(g_X)[n * 16 + l];
    float4 r;
    r.x = fmaf(ni, acc.x, 0.1f * x.x);
    r.y = fmaf(ni, acc.y, 0.1f * x.y);
    r.z = fmaf(ni, acc.z, 0.1f * x.z);
    r.w = fmaf(ni, acc.w, 0.1f * x.w);

    if (last) {
        reinterpret_cast<float4*>(g_z)[(size_t)p * N16 + n * 16 + l] = r;
    } else {
        float no = g_no[n];
        uint2* wr = reinterpret_cast<uint2*>(rdA ? g_sfB : g_sfA);
        wr[n * 16 + l] = pack4h(r.x * no, r.y * no, r.z * no, r.w * no);
    }
}

// semantic fusion: one warp per node-path, W1 staged in shared
__global__ void k_fusion(const float* __restrict__ W1, const float* __restrict__ b1,
                         const float* __restrict__ W2) {
    __shared__ __align__(16) float W1s[FEAT * HIDDEN];   // 32 KB
    __shared__ float zs[8][FEAT];                        // 2 KB
    int tid = threadIdx.x;
    for (int i = tid; i < FEAT * HIDDEN; i += blockDim.x) W1s[i] = W1[i];
    __syncthreads();

    int lane = tid & 31;
    int w = tid >> 5;
    float4 b4 = reinterpret_cast<const float4*>(b1)[lane];
    float4 w24 = reinterpret_cast<const float4*>(W2)[lane];
    int warpsTotal = gridDim.x * 8;

    for (int np = blockIdx.x * 8 + w; np < NPATH * N_NODES; np += warpsTotal) {
        float2 v = reinterpret_cast<const float2*>(g_z)[(size_t)np * 32 + lane];
        zs[w][2 * lane] = v.x;
        zs[w][2 * lane + 1] = v.y;
        __syncwarp();
        float4 acc = make_float4(0.f, 0.f, 0.f, 0.f);
#pragma unroll
        for (int j = 0; j < FEAT; j++) {
            float zj = zs[w][j];
            float4 ww = reinterpret_cast<const float4*>(W1s)[j * 32 + lane];
            acc.x = fmaf(zj, ww.x, acc.x);
            acc.y = fmaf(zj, ww.y, acc.y);
            acc.z = fmaf(zj, ww.z, acc.z);
            acc.w = fmaf(zj, ww.w, acc.w);
        }
        __syncwarp();
        float s = tanh_fast(acc.x + b4.x) * w24.x
                + tanh_fast(acc.y + b4.y) * w24.y
                + tanh_fast(acc.z + b4.z) * w24.z
                + tanh_fast(acc.w + b4.w) * w24.w;
#pragma unroll
        for (int o = 16; o; o >>= 1) s += __shfl_xor_sync(0xffffffffu, s, o);
        if (lane == 0) atomicAdd(&g_wsum[np / N_NODES], s);
    }
}

__global__ void k_beta() {
    if (threadIdx.x == 0) {
        float w0 = g_wsum[0] / (float)N_NODES;
        float w1 = g_wsum[1] / (float)N_NODES;
        float w2 = g_wsum[2] / (float)N_NODES;
        float m = fmaxf(w0, fmaxf(w1, w2));
        float e0 = expf(w0 - m), e1 = expf(w1 - m), e2 = expf(w2 - m);
        float inv = 1.f / (e0 + e1 + e2);
        g_beta[0] = e0 * inv; g_beta[1] = e1 * inv; g_beta[2] = e2 * inv;
    }
}

__global__ void k_out(float4* __restrict__ out) {
    int i = blockIdx.x * blockDim.x + threadIdx.x;
    if (i < N16) {
        float b0 = g_beta[0], b1 = g_beta[1], b2 = g_beta[2];
        const float4* z = reinterpret_cast<const float4*>(g_z);
        float4 z0 = z[i];
        float4 z1 = z[N16 + i];
        float4 z2 = z[2 * (size_t)N16 + i];
        float4 r;
        r.x = b0 * z0.x + b1 * z1.x + b2 * z2.x;
        r.y = b0 * z0.y + b1 * z1.y + b2 * z2.y;
        r.z = b0 * z0.z + b1 * z1.z + b2 * z2.z;
        r.w = b0 * z0.w + b1 * z1.w + b2 * z2.w;
        out[i] = r;
    }
}

// ---------------- launch ----------------
extern "C" void kernel_launch(void* const* d_in, const int* in_sizes, int n_in,
                              void* d_out, int out_size) {
    const float* h  = (const float*)d_in[0];
    const int* src  = (const int*)d_in[1];   // JAX x64-disabled -> int32
    const int* dst  = (const int*)d_in[2];
    const float* W1 = (const float*)d_in[3];
    const float* b1 = (const float*)d_in[4];
    const float* W2 = (const float*)d_in[5];

    const int TB = 256;
    const int gElem = (N16 + TB - 1) / TB;               // 6250
    const int gNode = (N_NODES + TB - 1) / TB;           // 391
    const int gEdge = (EPP + TB - 1) / TB;               // 12500
    const int gGath = (int)(((long long)N_NODES * 16 + TB - 1) / TB);  // 6250

    k_relu<<<gElem, TB>>>((const float4*)h);

    for (int p = 0; p < NPATH; p++) {
        const int* sp = src + (size_t)p * EPP;
        const int* dp = dst + (size_t)p * EPP;

        k_zero_deg<<<gNode, TB>>>();
        k_deg<<<gEdge, TB>>>(sp, dp);
        k_norm<<<gNode, TB>>>();

        // CSR build (by dst), amortized over 3 steps
        k_bsum<<<NBLK, 256>>>();
        k_bscan<<<1, 512>>>();
        k_offsets<<<NBLK, 256>>>();
        k_fill<<<gEdge, TB>>>(sp, dp);

        k_prescale0<<<gElem, TB>>>();
        // ping-pong: A -> B -> A -> z  (read-set / write-set disjoint each step)
        k_gather<<<gGath, TB>>>(1, 0, p);   // read A, write B
        k_gather<<<gGath, TB>>>(0, 0, p);   // read B, write A
        k_gather<<<gGath, TB>>>(1, 1, p);   // read A, write z
    }

    k_fusion<<<1184, 256>>>(W1, b1, W2);
    k_beta<<<1, 32>>>();
    k_out<<<gElem, TB>>>((float4*)d_out);
}